// round 11
// baseline (speedup 1.0000x reference)
#include <cuda_runtime.h>
#include <cuda_fp16.h>
#include <cstdint>
#include <math.h>

#define D_HID 2048
#define INTER 1408
#define NGU   2816
#define NEXP  8
#define TMAX  4096
#define TPAIR 8192
#define RMAX  9216

// ---------------- device scratch ----------------
__device__ int   g_count[NEXP];
__device__ int   g_top_e[TPAIR];
__device__ int   g_pos[TPAIR];
__device__ int   g_p2s[TPAIR];
__device__ float g_wt[TPAIR];
__device__ __align__(256) __half g_xg  [(size_t)RMAX * D_HID];
__device__ __align__(256) __half g_gup [(size_t)NEXP * NGU * D_HID];
__device__ __align__(256) __half g_dwn [(size_t)NEXP * D_HID * INTER];
__device__ __align__(256) __half g_h   [(size_t)RMAX * INTER];
__device__ __align__(256) float  g_ct  [(size_t)RMAX * D_HID];

// ---------------- helpers ----------------
__device__ __forceinline__ uint32_t smem_u32(const void* p) {
    uint32_t a;
    asm("{ .reg .u64 t; cvta.to.shared.u64 t, %1; cvt.u32.u64 %0, t; }" : "=r"(a) : "l"(p));
    return a;
}
__device__ __forceinline__ void cp16z(uint32_t dst, const void* src, uint32_t sz) {
    asm volatile("cp.async.cg.shared.global [%0], [%1], 16, %2;"
                 :: "r"(dst), "l"(src), "r"(sz));
}
__device__ __forceinline__ void ldsm4(uint32_t* r, uint32_t addr) {
    asm volatile("ldmatrix.sync.aligned.m8n8.x4.shared.b16 {%0,%1,%2,%3}, [%4];"
                 : "=r"(r[0]), "=r"(r[1]), "=r"(r[2]), "=r"(r[3]) : "r"(addr));
}
__device__ __forceinline__ void mma_f16(float* d, const uint32_t* a, const uint32_t* b) {
    asm volatile("mma.sync.aligned.m16n8k16.row.col.f32.f16.f16.f32 "
                 "{%0,%1,%2,%3}, {%4,%5,%6,%7}, {%8,%9}, {%0,%1,%2,%3};"
                 : "+f"(d[0]), "+f"(d[1]), "+f"(d[2]), "+f"(d[3])
                 : "r"(a[0]), "r"(a[1]), "r"(a[2]), "r"(a[3]), "r"(b[0]), "r"(b[1]));
}
__device__ __forceinline__ int expert_base(int e) {
    int o = 0;
#pragma unroll
    for (int k = 0; k < NEXP; k++)
        if (k < e) o += (g_count[k] + 127) & ~127;
    return o;
}

// ---------------- init ----------------
__global__ void zero_counts_kernel() {
    if (threadIdx.x < NEXP) g_count[threadIdx.x] = 0;
}

// ---------------- router ----------------
__global__ void router_kernel(const float* __restrict__ x,
                              const float* __restrict__ rw) {
    int t = blockIdx.x;
    const float* xr = x + (size_t)t * D_HID;
    float p[NEXP];
#pragma unroll
    for (int e = 0; e < NEXP; e++) p[e] = 0.f;
    for (int d = threadIdx.x; d < D_HID; d += blockDim.x) {
        float xv = xr[d];
#pragma unroll
        for (int e = 0; e < NEXP; e++)
            p[e] = fmaf(xv, rw[e * D_HID + d], p[e]);
    }
#pragma unroll
    for (int off = 16; off > 0; off >>= 1)
#pragma unroll
        for (int e = 0; e < NEXP; e++)
            p[e] += __shfl_down_sync(0xffffffffu, p[e], off);
    __shared__ float s[8][NEXP];
    int warp = threadIdx.x >> 5;
    if ((threadIdx.x & 31) == 0)
#pragma unroll
        for (int e = 0; e < NEXP; e++) s[warp][e] = p[e];
    __syncthreads();
    if (threadIdx.x == 0) {
        float l[NEXP];
#pragma unroll
        for (int e = 0; e < NEXP; e++) {
            float a = 0.f;
#pragma unroll
            for (int w = 0; w < 8; w++) a += s[w][e];
            l[e] = a;
        }
        int i0 = 0;
#pragma unroll
        for (int e = 1; e < NEXP; e++) if (l[e] > l[i0]) i0 = e;
        int i1 = (i0 == 0) ? 1 : 0;
#pragma unroll
        for (int e = 0; e < NEXP; e++)
            if (e != i0 && l[e] > l[i1]) i1 = e;
        float e1  = expf(l[i1] - l[i0]);
        float inv = 1.f / (1.f + e1);
        g_wt[2*t]   = inv;
        g_wt[2*t+1] = e1 * inv;
        int p0 = atomicAdd(&g_count[i0], 1);
        g_top_e[2*t] = i0; g_pos[2*t] = p0;
        int p1 = atomicAdd(&g_count[i1], 1);
        g_top_e[2*t+1] = i1; g_pos[2*t+1] = p1;
    }
}

// ---------------- prep: gather-x (fp16) + weight fp16 conversions ----------
__global__ void prep_kernel(const float* __restrict__ x,
                            const float* __restrict__ gup,
                            const float* __restrict__ dwn) {
    int b = blockIdx.x;
    if (b < TPAIR) {
        int p = b;
        int t = p >> 1;
        int s = expert_base(g_top_e[p]) + g_pos[p];
        if (threadIdx.x == 0) g_p2s[p] = s;
        const float4* src = (const float4*)(x + (size_t)t * D_HID);
        __half2* dh = (__half2*)(g_xg + (size_t)s * D_HID);
        for (int i = threadIdx.x; i < D_HID/4; i += blockDim.x) {
            float4 v = src[i];
            dh[2*i]   = __halves2half2(__float2half(v.x), __float2half(v.y));
            dh[2*i+1] = __halves2half2(__float2half(v.z), __float2half(v.w));
        }
    } else if (b < TPAIR + NEXP * NGU) {
        int row = b - TPAIR;
        int e = row / NGU;
        int n = row % NGU;
        int blk = n >> 6, r = n & 63;
        int src_n = (r < 32) ? (blk*32 + r) : (INTER + blk*32 + (r - 32));
        const float4* src = (const float4*)(gup + ((size_t)e * NGU + src_n) * D_HID);
        __half2* dh = (__half2*)(g_gup + (size_t)row * D_HID);
        for (int i = threadIdx.x; i < D_HID/4; i += blockDim.x) {
            float4 v = src[i];
            dh[2*i]   = __halves2half2(__float2half(v.x), __float2half(v.y));
            dh[2*i+1] = __halves2half2(__float2half(v.z), __float2half(v.w));
        }
    } else {
        int row = b - TPAIR - NEXP * NGU;
        const float4* src = (const float4*)(dwn + (size_t)row * INTER);
        __half2* dh = (__half2*)(g_dwn + (size_t)row * INTER);
        for (int i = threadIdx.x; i < INTER/4; i += blockDim.x) {
            float4 v = src[i];
            dh[2*i]   = __halves2half2(__float2half(v.x), __float2half(v.y));
            dh[2*i+1] = __halves2half2(__float2half(v.z), __float2half(v.w));
        }
    }
}

// ---------------- HMMA grouped GEMM (pure fp16, warp tile 64x64) -----------
// CTA tile 128x128, 128 threads (4 warps: 2 in M x 2 in N), 2 CTAs/SM
// K-chunk 64 as two K=32 subtiles; 2-stage pipeline.
// PHASE 0: A = g_xg, fused SwiGLU epilogue -> g_h (fp16)
// PHASE 1: A = g_h,  fp32 epilogue -> g_ct
#define PITCH 80
#define A_TILE (128*PITCH)           // 10240 (one K=32 subtile, A or B)
#define STAGE  (4*A_TILE)            // 40960: [A0|A1|B0|B1]
#define NSTG   2
#define GEMM_SMEM (NSTG*STAGE)       // 81920

template <int PHASE>
__global__ void __launch_bounds__(128, 2)
moe_gemm_kernel() {
    constexpr int Kd  = (PHASE == 0) ? D_HID : INTER;   // 2048 / 1408
    constexpr int NCH = Kd / 64;                        // 32 / 22
    constexpr int NROW = (PHASE == 0) ? NGU : D_HID;

    int e   = blockIdx.z;
    int cnt = g_count[e];
    int m0  = blockIdx.x * 128;
    if (m0 >= cnt) return;
    int n0  = blockIdx.y * 128;
    int off_e = expert_base(e);

    const __half* A = ((PHASE == 0) ? g_xg : g_h) + (size_t)(off_e + m0) * Kd;
    const __half* B = ((PHASE == 0) ? g_gup : g_dwn) + ((size_t)e * NROW + n0) * Kd;

    extern __shared__ __align__(128) char smem[];
    uint32_t sb = smem_u32(smem);

    int tid = threadIdx.x;
    int wid = tid >> 5;
    int lid = tid & 31;
    int warp_m = (wid >> 1) * 64;     // 0,64
    int warp_n = (wid & 1) * 64;      // 0,64

    uint32_t a_off = (uint32_t)((warp_m + (lid & 15)) * PITCH + (lid >> 4) * 16);
    uint32_t b_off = (uint32_t)((warp_n + (lid & 7) + ((lid & 16) >> 1)) * PITCH +
                                ((lid >> 3) & 1) * 16);

    float d[4][8][4];
#pragma unroll
    for (int mi = 0; mi < 4; mi++)
#pragma unroll
        for (int ni = 0; ni < 8; ni++)
#pragma unroll
            for (int k = 0; k < 4; k++) d[mi][ni][k] = 0.f;

    // chunk = 64 K elements = 128 bytes; two 64B subtiles at +0 and +64.
    // 128 threads, 4 ops each per (A,B) pair of subtiles x 4 groups.
    auto load_chunk = [&](int ci, int s) {
        uint32_t st = sb + s * STAGE;
        size_t go = (size_t)ci * 128;
#pragma unroll
        for (int k = 0; k < 4; k++) {
            int idx = tid + k * 128;
            int r = idx >> 2, q = idx & 3;
            uint32_t so = (uint32_t)(r * PITCH + q * 16);
            const char* pa = (const char*)(A + (size_t)r * Kd + q * 8);
            const char* pb = (const char*)(B + (size_t)r * Kd + q * 8);
            uint32_t sz = (m0 + r < cnt) ? 16u : 0u;
            cp16z(st + so,            pa + go,      sz);
            cp16z(st + A_TILE + so,   pa + go + 64, sz);
            cp16z(st + 2*A_TILE + so, pb + go,      16u);
            cp16z(st + 3*A_TILE + so, pb + go + 64, 16u);
        }
    };

    load_chunk(0, 0);
    asm volatile("cp.async.commit_group;" ::: "memory");

#pragma unroll 1
    for (int i = 0; i < NCH; i++) {
        asm volatile("cp.async.wait_group 0;" ::: "memory");
        __syncthreads();
        if (i + 1 < NCH) {
            load_chunk(i + 1, (i + 1) & 1);
            asm volatile("cp.async.commit_group;" ::: "memory");
        }
        uint32_t st = sb + (i & 1) * STAGE;
#pragma unroll
        for (int sl = 0; sl < 4; sl++) {           // 4 K=16 slices
            uint32_t ab = st + (sl >> 1) * A_TILE;
            uint32_t bb = st + (2 + (sl >> 1)) * A_TILE;
            uint32_t ko = (sl & 1) * 32;
            uint32_t af[4][4];
#pragma unroll
            for (int mi = 0; mi < 4; mi++)
                ldsm4(af[mi], ab + a_off + ko + mi * 16 * PITCH);
#pragma unroll
            for (int pp = 0; pp < 2; pp++) {
                uint32_t bf[2][4];
                ldsm4(bf[0], bb + b_off + ko + (pp*2 + 0) * 16 * PITCH);
                ldsm4(bf[1], bb + b_off + ko + (pp*2 + 1) * 16 * PITCH);
#pragma unroll
                for (int mi = 0; mi < 4; mi++)
#pragma unroll
                    for (int q = 0; q < 4; q++)
                        mma_f16(d[mi][pp*4 + q], af[mi], &bf[q >> 1][(q & 1) * 2]);
            }
        }
    }

    // ---------------- epilogue ----------------
    if (PHASE == 0) {
        int icb = blockIdx.y * 64 + (warp_n >> 1);
#pragma unroll
        for (int mi = 0; mi < 4; mi++) {
            int rA = warp_m + mi * 16 + (lid >> 2);
            int rB = rA + 8;
            bool vA = (m0 + rA) < cnt;
            bool vB = (m0 + rB) < cnt;
            size_t rowA = (size_t)(off_e + m0 + rA);
            size_t rowB = (size_t)(off_e + m0 + rB);
#pragma unroll
            for (int ni = 0; ni < 4; ni++) {
                int col = icb + ni * 8 + (lid & 3) * 2;
                const float* g = d[mi][ni];
                const float* u = d[mi][ni + 4];
                if (vA) {
                    float h0 = g[0] / (1.f + expf(-g[0])) * u[0];
                    float h1 = g[1] / (1.f + expf(-g[1])) * u[1];
                    *(__half2*)(g_h + rowA * INTER + col) =
                        __halves2half2(__float2half(h0), __float2half(h1));
                }
                if (vB) {
                    float h0 = g[2] / (1.f + expf(-g[2])) * u[2];
                    float h1 = g[3] / (1.f + expf(-g[3])) * u[3];
                    *(__half2*)(g_h + rowB * INTER + col) =
                        __halves2half2(__float2half(h0), __float2half(h1));
                }
            }
        }
    } else {
#pragma unroll
        for (int mi = 0; mi < 4; mi++) {
            int rA = warp_m + mi * 16 + (lid >> 2);
            int rB = rA + 8;
            bool vA = (m0 + rA) < cnt;
            bool vB = (m0 + rB) < cnt;
            float* cA = g_ct + (size_t)(off_e + m0 + rA) * D_HID + n0 + warp_n + (lid & 3) * 2;
            float* cB = g_ct + (size_t)(off_e + m0 + rB) * D_HID + n0 + warp_n + (lid & 3) * 2;
#pragma unroll
            for (int ni = 0; ni < 8; ni++) {
                if (vA) { float2 v; v.x = d[mi][ni][0]; v.y = d[mi][ni][1];
                          *(float2*)(cA + ni * 8) = v; }
                if (vB) { float2 v; v.x = d[mi][ni][2]; v.y = d[mi][ni][3];
                          *(float2*)(cB + ni * 8) = v; }
            }
        }
    }
}

// ---------------- combine ----------------
__global__ void combine_kernel(float* __restrict__ out, int total4) {
    int i = blockIdx.x * blockDim.x + threadIdx.x;
    if (i >= total4) return;
    int c = i % (D_HID/4);
    int t = i / (D_HID/4);
    float w0 = g_wt[2*t], w1 = g_wt[2*t+1];
    int s0 = g_p2s[2*t], s1 = g_p2s[2*t+1];
    float4 c0 = ((const float4*)(g_ct + (size_t)s0 * D_HID))[c];
    float4 c1 = ((const float4*)(g_ct + (size_t)s1 * D_HID))[c];
    float4 o;
    o.x = fmaf(w0, c0.x, w1 * c1.x);
    o.y = fmaf(w0, c0.y, w1 * c1.y);
    o.z = fmaf(w0, c0.z, w1 * c1.z);
    o.w = fmaf(w0, c0.w, w1 * c1.w);
    ((float4*)out)[i] = o;
}

// ---------------- launch ----------------
extern "C" void kernel_launch(void* const* d_in, const int* in_sizes, int n_in,
                              void* d_out, int out_size) {
    const float* x   = (const float*)d_in[0];
    const float* rw  = (const float*)d_in[1];
    const float* gup = (const float*)d_in[2];
    const float* dwn = (const float*)d_in[3];
    float* out = (float*)d_out;
    int T = in_sizes[0] / D_HID;

    cudaFuncSetAttribute(moe_gemm_kernel<0>, cudaFuncAttributeMaxDynamicSharedMemorySize, GEMM_SMEM);
    cudaFuncSetAttribute(moe_gemm_kernel<1>, cudaFuncAttributeMaxDynamicSharedMemorySize, GEMM_SMEM);

    zero_counts_kernel<<<1, 32>>>();                       // 0
    router_kernel<<<T, 256>>>(x, rw);                      // 1
    int prep_blocks = TPAIR + NEXP * NGU + NEXP * D_HID;
    prep_kernel<<<prep_blocks, 128>>>(x, gup, dwn);        // 2

    dim3 g0(32, NGU / 128, NEXP);                          // 3 (GEMM1 @ index 3)
    moe_gemm_kernel<0><<<g0, 128, GEMM_SMEM>>>();

    dim3 g1(32, D_HID / 128, NEXP);                        // 4
    moe_gemm_kernel<1><<<g1, 128, GEMM_SMEM>>>();

    combine_kernel<<<(T * (D_HID/4) + 255) / 256, 256>>>(out, T * (D_HID/4)); // 5
}

// round 12
// speedup vs baseline: 1.3067x; 1.3067x over previous
#include <cuda_runtime.h>
#include <cuda_fp16.h>
#include <cstdint>
#include <math.h>

#define D_HID 2048
#define INTER 1408
#define NGU   2816
#define NEXP  8
#define TMAX  4096
#define TPAIR 8192
#define RMAX  9216

// ---------------- device scratch ----------------
__device__ int   g_count[NEXP];
__device__ int   g_top_e[TPAIR];
__device__ int   g_pos[TPAIR];
__device__ int   g_p2s[TPAIR];
__device__ float g_wt[TPAIR];
__device__ __align__(256) __half g_xg  [(size_t)RMAX * D_HID];
__device__ __align__(256) __half g_gup [(size_t)NEXP * NGU * D_HID];
__device__ __align__(256) __half g_dwn [(size_t)NEXP * D_HID * INTER];
__device__ __align__(256) __half g_h   [(size_t)RMAX * INTER];
__device__ __align__(256) float  g_ct  [(size_t)RMAX * D_HID];

// ---------------- helpers ----------------
__device__ __forceinline__ uint32_t smem_u32(const void* p) {
    uint32_t a;
    asm("{ .reg .u64 t; cvta.to.shared.u64 t, %1; cvt.u32.u64 %0, t; }" : "=r"(a) : "l"(p));
    return a;
}
__device__ __forceinline__ void cp16z(uint32_t dst, const void* src, uint32_t sz) {
    asm volatile("cp.async.cg.shared.global [%0], [%1], 16, %2;"
                 :: "r"(dst), "l"(src), "r"(sz));
}
__device__ __forceinline__ void ldsm4(uint32_t* r, uint32_t addr) {
    asm volatile("ldmatrix.sync.aligned.m8n8.x4.shared.b16 {%0,%1,%2,%3}, [%4];"
                 : "=r"(r[0]), "=r"(r[1]), "=r"(r[2]), "=r"(r[3]) : "r"(addr));
}
__device__ __forceinline__ void mma_f16(float* d, const uint32_t* a, const uint32_t* b) {
    asm volatile("mma.sync.aligned.m16n8k16.row.col.f32.f16.f16.f32 "
                 "{%0,%1,%2,%3}, {%4,%5,%6,%7}, {%8,%9}, {%0,%1,%2,%3};"
                 : "+f"(d[0]), "+f"(d[1]), "+f"(d[2]), "+f"(d[3])
                 : "r"(a[0]), "r"(a[1]), "r"(a[2]), "r"(a[3]), "r"(b[0]), "r"(b[1]));
}
__device__ __forceinline__ int expert_base(int e) {
    int o = 0;
#pragma unroll
    for (int k = 0; k < NEXP; k++)
        if (k < e) o += (g_count[k] + 127) & ~127;
    return o;
}

// ---------------- init ----------------
__global__ void zero_counts_kernel() {
    if (threadIdx.x < NEXP) g_count[threadIdx.x] = 0;
}

// ---------------- router ----------------
__global__ void router_kernel(const float* __restrict__ x,
                              const float* __restrict__ rw) {
    int t = blockIdx.x;
    const float* xr = x + (size_t)t * D_HID;
    float p[NEXP];
#pragma unroll
    for (int e = 0; e < NEXP; e++) p[e] = 0.f;
    for (int d = threadIdx.x; d < D_HID; d += blockDim.x) {
        float xv = xr[d];
#pragma unroll
        for (int e = 0; e < NEXP; e++)
            p[e] = fmaf(xv, rw[e * D_HID + d], p[e]);
    }
#pragma unroll
    for (int off = 16; off > 0; off >>= 1)
#pragma unroll
        for (int e = 0; e < NEXP; e++)
            p[e] += __shfl_down_sync(0xffffffffu, p[e], off);
    __shared__ float s[8][NEXP];
    int warp = threadIdx.x >> 5;
    if ((threadIdx.x & 31) == 0)
#pragma unroll
        for (int e = 0; e < NEXP; e++) s[warp][e] = p[e];
    __syncthreads();
    if (threadIdx.x == 0) {
        float l[NEXP];
#pragma unroll
        for (int e = 0; e < NEXP; e++) {
            float a = 0.f;
#pragma unroll
            for (int w = 0; w < 8; w++) a += s[w][e];
            l[e] = a;
        }
        int i0 = 0;
#pragma unroll
        for (int e = 1; e < NEXP; e++) if (l[e] > l[i0]) i0 = e;
        int i1 = (i0 == 0) ? 1 : 0;
#pragma unroll
        for (int e = 0; e < NEXP; e++)
            if (e != i0 && l[e] > l[i1]) i1 = e;
        float e1  = expf(l[i1] - l[i0]);
        float inv = 1.f / (1.f + e1);
        g_wt[2*t]   = inv;
        g_wt[2*t+1] = e1 * inv;
        int p0 = atomicAdd(&g_count[i0], 1);
        g_top_e[2*t] = i0; g_pos[2*t] = p0;
        int p1 = atomicAdd(&g_count[i1], 1);
        g_top_e[2*t+1] = i1; g_pos[2*t+1] = p1;
    }
}

// ---------------- prep: gather-x (fp16) + weight fp16 conversions ----------
__global__ void prep_kernel(const float* __restrict__ x,
                            const float* __restrict__ gup,
                            const float* __restrict__ dwn) {
    int b = blockIdx.x;
    if (b < TPAIR) {
        int p = b;
        int t = p >> 1;
        int s = expert_base(g_top_e[p]) + g_pos[p];
        if (threadIdx.x == 0) g_p2s[p] = s;
        const float4* src = (const float4*)(x + (size_t)t * D_HID);
        __half2* dh = (__half2*)(g_xg + (size_t)s * D_HID);
        for (int i = threadIdx.x; i < D_HID/4; i += blockDim.x) {
            float4 v = src[i];
            dh[2*i]   = __halves2half2(__float2half(v.x), __float2half(v.y));
            dh[2*i+1] = __halves2half2(__float2half(v.z), __float2half(v.w));
        }
    } else if (b < TPAIR + NEXP * NGU) {
        int row = b - TPAIR;
        int e = row / NGU;
        int n = row % NGU;
        int blk = n >> 6, r = n & 63;
        int src_n = (r < 32) ? (blk*32 + r) : (INTER + blk*32 + (r - 32));
        const float4* src = (const float4*)(gup + ((size_t)e * NGU + src_n) * D_HID);
        __half2* dh = (__half2*)(g_gup + (size_t)row * D_HID);
        for (int i = threadIdx.x; i < D_HID/4; i += blockDim.x) {
            float4 v = src[i];
            dh[2*i]   = __halves2half2(__float2half(v.x), __float2half(v.y));
            dh[2*i+1] = __halves2half2(__float2half(v.z), __float2half(v.w));
        }
    } else {
        int row = b - TPAIR - NEXP * NGU;
        const float4* src = (const float4*)(dwn + (size_t)row * INTER);
        __half2* dh = (__half2*)(g_dwn + (size_t)row * INTER);
        for (int i = threadIdx.x; i < INTER/4; i += blockDim.x) {
            float4 v = src[i];
            dh[2*i]   = __halves2half2(__float2half(v.x), __float2half(v.y));
            dh[2*i+1] = __halves2half2(__float2half(v.z), __float2half(v.w));
        }
    }
}

// ---------------- HMMA grouped GEMM (pure fp16, SW128 smem layout) ---------
// CTA tile 128x128, 256 threads (8 warps: 4 in M x 2 in N), 2 CTAs/SM
// K-chunk 64 stored as 128 rows x 128B (SW128 XOR swizzle); 3-stage pipeline.
// PHASE 0: A = g_xg, fused SwiGLU epilogue -> g_h (fp16)
// PHASE 1: A = g_h,  fp32 epilogue -> g_ct
#define TILEB  16384                 // 128 rows x 128 B (one K=64 operand tile)
#define STAGE  (2*TILEB)             // 32768: [A|B]
#define NSTG   3
#define GEMM_SMEM (NSTG*STAGE)       // 98304

template <int PHASE>
__global__ void __launch_bounds__(256, 2)
moe_gemm_kernel() {
    constexpr int Kd  = (PHASE == 0) ? D_HID : INTER;   // 2048 / 1408
    constexpr int NCH = Kd / 64;                        // 32 / 22
    constexpr int NROW = (PHASE == 0) ? NGU : D_HID;

    int e   = blockIdx.z;
    int cnt = g_count[e];
    int m0  = blockIdx.x * 128;
    if (m0 >= cnt) return;
    int n0  = blockIdx.y * 128;
    int off_e = expert_base(e);

    const __half* A = ((PHASE == 0) ? g_xg : g_h) + (size_t)(off_e + m0) * Kd;
    const __half* B = ((PHASE == 0) ? g_gup : g_dwn) + ((size_t)e * NROW + n0) * Kd;

    extern __shared__ __align__(128) char smem[];
    uint32_t sb = smem_u32(smem);

    int tid = threadIdx.x;
    int wid = tid >> 5;
    int lid = tid & 31;
    int warp_m = (wid >> 1) * 32;     // 0,32,64,96
    int warp_n = (wid & 1) * 64;      // 0,64

    // ldsm per-lane bases (SW128): addr(r,q) = r*128 + ((q ^ (r&7))<<4)
    uint32_t m7 = (uint32_t)(lid & 7) << 4;
    uint32_t a_base = (uint32_t)(warp_m + (lid & 15)) * 128 + m7;
    uint32_t a_dq   = (uint32_t)(lid >> 4);            // 0/1
    uint32_t b_base = (uint32_t)(warp_n + (lid & 7) + ((lid & 16) >> 1)) * 128 + m7;
    uint32_t b_dq   = (uint32_t)((lid >> 3) & 1);      // 0/1

    float d[2][8][4];
#pragma unroll
    for (int mi = 0; mi < 2; mi++)
#pragma unroll
        for (int ni = 0; ni < 8; ni++)
#pragma unroll
            for (int k = 0; k < 4; k++) d[mi][ni][k] = 0.f;

    // chunk = 64 K elems = one 128B row per tile row; 8 quads per row.
    auto load_chunk = [&](int ci, int s) {
        uint32_t st = sb + s * STAGE;
        size_t go = (size_t)ci * 64;   // K offset in halves
#pragma unroll
        for (int k = 0; k < 4; k++) {
            int idx = tid + k * 256;       // 0..1023
            int r = idx >> 3, q = idx & 7;
            uint32_t dst = st + (uint32_t)(r * 128 + (((q ^ (r & 7)) << 4)));
            const char* pa = (const char*)(A + (size_t)r * Kd + go + q * 8);
            const char* pb = (const char*)(B + (size_t)r * Kd + go + q * 8);
            uint32_t sz = (m0 + r < cnt) ? 16u : 0u;
            cp16z(dst,         pa, sz);
            cp16z(dst + TILEB, pb, 16u);
        }
    };

    load_chunk(0, 0);
    asm volatile("cp.async.commit_group;" ::: "memory");
    if (NCH > 1) load_chunk(1, 1);
    asm volatile("cp.async.commit_group;" ::: "memory");

    int sidx = 0, lidx = 2;
#pragma unroll 1
    for (int i = 0; i < NCH; i++) {
        if (i == NCH - 1) {
            asm volatile("cp.async.wait_group 0;" ::: "memory");
        } else {
            asm volatile("cp.async.wait_group 1;" ::: "memory");
        }
        __syncthreads();
        if (i + 2 < NCH) {
            load_chunk(i + 2, lidx);
            asm volatile("cp.async.commit_group;" ::: "memory");
        }
        uint32_t st = sb + sidx * STAGE;
#pragma unroll
        for (int sl = 0; sl < 4; sl++) {           // 4 K=16 slices
            uint32_t qa = (uint32_t)(2*sl + a_dq) << 4;
            uint32_t qb = (uint32_t)(2*sl + b_dq) << 4;
            uint32_t af[2][4];
            ldsm4(af[0], st + (a_base ^ qa));
            ldsm4(af[1], st + ((a_base + 2048) ^ qa));
#pragma unroll
            for (int pp = 0; pp < 2; pp++) {
                uint32_t bf[2][4];
                ldsm4(bf[0], st + TILEB + ((b_base + (pp*2 + 0)*2048) ^ qb));
                ldsm4(bf[1], st + TILEB + ((b_base + (pp*2 + 1)*2048) ^ qb));
#pragma unroll
                for (int mi = 0; mi < 2; mi++)
#pragma unroll
                    for (int q = 0; q < 4; q++)
                        mma_f16(d[mi][pp*4 + q], af[mi], &bf[q >> 1][(q & 1) * 2]);
            }
        }
        sidx = (sidx == NSTG-1) ? 0 : sidx + 1;
        lidx = (lidx == NSTG-1) ? 0 : lidx + 1;
    }

    // ---------------- epilogue ----------------
    if (PHASE == 0) {
        int icb = blockIdx.y * 64 + (warp_n >> 1);
#pragma unroll
        for (int mi = 0; mi < 2; mi++) {
            int rA = warp_m + mi * 16 + (lid >> 2);
            int rB = rA + 8;
            bool vA = (m0 + rA) < cnt;
            bool vB = (m0 + rB) < cnt;
            size_t rowA = (size_t)(off_e + m0 + rA);
            size_t rowB = (size_t)(off_e + m0 + rB);
#pragma unroll
            for (int ni = 0; ni < 4; ni++) {
                int col = icb + ni * 8 + (lid & 3) * 2;
                const float* g = d[mi][ni];
                const float* u = d[mi][ni + 4];
                if (vA) {
                    float h0 = g[0] / (1.f + expf(-g[0])) * u[0];
                    float h1 = g[1] / (1.f + expf(-g[1])) * u[1];
                    *(__half2*)(g_h + rowA * INTER + col) =
                        __halves2half2(__float2half(h0), __float2half(h1));
                }
                if (vB) {
                    float h0 = g[2] / (1.f + expf(-g[2])) * u[2];
                    float h1 = g[3] / (1.f + expf(-g[3])) * u[3];
                    *(__half2*)(g_h + rowB * INTER + col) =
                        __halves2half2(__float2half(h0), __float2half(h1));
                }
            }
        }
    } else {
#pragma unroll
        for (int mi = 0; mi < 2; mi++) {
            int rA = warp_m + mi * 16 + (lid >> 2);
            int rB = rA + 8;
            bool vA = (m0 + rA) < cnt;
            bool vB = (m0 + rB) < cnt;
            float* cA = g_ct + (size_t)(off_e + m0 + rA) * D_HID + n0 + warp_n + (lid & 3) * 2;
            float* cB = g_ct + (size_t)(off_e + m0 + rB) * D_HID + n0 + warp_n + (lid & 3) * 2;
#pragma unroll
            for (int ni = 0; ni < 8; ni++) {
                if (vA) { float2 v; v.x = d[mi][ni][0]; v.y = d[mi][ni][1];
                          *(float2*)(cA + ni * 8) = v; }
                if (vB) { float2 v; v.x = d[mi][ni][2]; v.y = d[mi][ni][3];
                          *(float2*)(cB + ni * 8) = v; }
            }
        }
    }
}

// ---------------- combine ----------------
__global__ void combine_kernel(float* __restrict__ out, int total4) {
    int i = blockIdx.x * blockDim.x + threadIdx.x;
    if (i >= total4) return;
    int c = i % (D_HID/4);
    int t = i / (D_HID/4);
    float w0 = g_wt[2*t], w1 = g_wt[2*t+1];
    int s0 = g_p2s[2*t], s1 = g_p2s[2*t+1];
    float4 c0 = ((const float4*)(g_ct + (size_t)s0 * D_HID))[c];
    float4 c1 = ((const float4*)(g_ct + (size_t)s1 * D_HID))[c];
    float4 o;
    o.x = fmaf(w0, c0.x, w1 * c1.x);
    o.y = fmaf(w0, c0.y, w1 * c1.y);
    o.z = fmaf(w0, c0.z, w1 * c1.z);
    o.w = fmaf(w0, c0.w, w1 * c1.w);
    ((float4*)out)[i] = o;
}

// ---------------- launch ----------------
extern "C" void kernel_launch(void* const* d_in, const int* in_sizes, int n_in,
                              void* d_out, int out_size) {
    const float* x   = (const float*)d_in[0];
    const float* rw  = (const float*)d_in[1];
    const float* gup = (const float*)d_in[2];
    const float* dwn = (const float*)d_in[3];
    float* out = (float*)d_out;
    int T = in_sizes[0] / D_HID;

    cudaFuncSetAttribute(moe_gemm_kernel<0>, cudaFuncAttributeMaxDynamicSharedMemorySize, GEMM_SMEM);
    cudaFuncSetAttribute(moe_gemm_kernel<1>, cudaFuncAttributeMaxDynamicSharedMemorySize, GEMM_SMEM);

    zero_counts_kernel<<<1, 32>>>();                       // 0
    router_kernel<<<T, 256>>>(x, rw);                      // 1
    int prep_blocks = TPAIR + NEXP * NGU + NEXP * D_HID;
    prep_kernel<<<prep_blocks, 128>>>(x, gup, dwn);        // 2

    dim3 g0(32, NGU / 128, NEXP);                          // 3 (GEMM1 @ index 3)
    moe_gemm_kernel<0><<<g0, 256, GEMM_SMEM>>>();

    dim3 g1(32, D_HID / 128, NEXP);                        // 4
    moe_gemm_kernel<1><<<g1, 256, GEMM_SMEM>>>();

    combine_kernel<<<(T * (D_HID/4) + 255) / 256, 256>>>(out, T * (D_HID/4)); // 5
}

// round 13
// speedup vs baseline: 1.3492x; 1.0325x over previous
#include <cuda_runtime.h>
#include <cuda_fp16.h>
#include <cstdint>
#include <math.h>

#define D_HID 2048
#define INTER 1408
#define NGU   2816
#define NEXP  8
#define TMAX  4096
#define TPAIR 8192
#define RMAX  9216

// ---------------- device scratch ----------------
__device__ int   g_count[NEXP];
__device__ int   g_top_e[TPAIR];
__device__ int   g_pos[TPAIR];
__device__ int   g_p2s[TPAIR];
__device__ int   g_s2t[RMAX];
__device__ float g_wt[TPAIR];
__device__ __align__(256) __half g_x16 [(size_t)TMAX * D_HID];
__device__ __align__(256) __half g_gup [(size_t)NEXP * NGU * D_HID];
__device__ __align__(256) __half g_dwn [(size_t)NEXP * D_HID * INTER];
__device__ __align__(256) __half g_h   [(size_t)RMAX * INTER];
__device__ __align__(256) __half g_ct  [(size_t)RMAX * D_HID];

// ---------------- helpers ----------------
__device__ __forceinline__ uint32_t smem_u32(const void* p) {
    uint32_t a;
    asm("{ .reg .u64 t; cvta.to.shared.u64 t, %1; cvt.u32.u64 %0, t; }" : "=r"(a) : "l"(p));
    return a;
}
__device__ __forceinline__ void cp16z(uint32_t dst, const void* src, uint32_t sz) {
    asm volatile("cp.async.cg.shared.global [%0], [%1], 16, %2;"
                 :: "r"(dst), "l"(src), "r"(sz));
}
__device__ __forceinline__ void ldsm4(uint32_t* r, uint32_t addr) {
    asm volatile("ldmatrix.sync.aligned.m8n8.x4.shared.b16 {%0,%1,%2,%3}, [%4];"
                 : "=r"(r[0]), "=r"(r[1]), "=r"(r[2]), "=r"(r[3]) : "r"(addr));
}
__device__ __forceinline__ void mma_f16(float* d, const uint32_t* a, const uint32_t* b) {
    asm volatile("mma.sync.aligned.m16n8k16.row.col.f32.f16.f16.f32 "
                 "{%0,%1,%2,%3}, {%4,%5,%6,%7}, {%8,%9}, {%0,%1,%2,%3};"
                 : "+f"(d[0]), "+f"(d[1]), "+f"(d[2]), "+f"(d[3])
                 : "r"(a[0]), "r"(a[1]), "r"(a[2]), "r"(a[3]), "r"(b[0]), "r"(b[1]));
}
__device__ __forceinline__ int expert_base(int e) {
    int o = 0;
#pragma unroll
    for (int k = 0; k < NEXP; k++)
        if (k < e) o += (g_count[k] + 127) & ~127;
    return o;
}

// ---------------- init ----------------
__global__ void zero_counts_kernel() {
    if (threadIdx.x < NEXP) g_count[threadIdx.x] = 0;
}

// ---------------- router ----------------
__global__ void router_kernel(const float* __restrict__ x,
                              const float* __restrict__ rw) {
    int t = blockIdx.x;
    const float* xr = x + (size_t)t * D_HID;
    float p[NEXP];
#pragma unroll
    for (int e = 0; e < NEXP; e++) p[e] = 0.f;
    for (int d = threadIdx.x; d < D_HID; d += blockDim.x) {
        float xv = xr[d];
#pragma unroll
        for (int e = 0; e < NEXP; e++)
            p[e] = fmaf(xv, rw[e * D_HID + d], p[e]);
    }
#pragma unroll
    for (int off = 16; off > 0; off >>= 1)
#pragma unroll
        for (int e = 0; e < NEXP; e++)
            p[e] += __shfl_down_sync(0xffffffffu, p[e], off);
    __shared__ float s[8][NEXP];
    int warp = threadIdx.x >> 5;
    if ((threadIdx.x & 31) == 0)
#pragma unroll
        for (int e = 0; e < NEXP; e++) s[warp][e] = p[e];
    __syncthreads();
    if (threadIdx.x == 0) {
        float l[NEXP];
#pragma unroll
        for (int e = 0; e < NEXP; e++) {
            float a = 0.f;
#pragma unroll
            for (int w = 0; w < 8; w++) a += s[w][e];
            l[e] = a;
        }
        int i0 = 0;
#pragma unroll
        for (int e = 1; e < NEXP; e++) if (l[e] > l[i0]) i0 = e;
        int i1 = (i0 == 0) ? 1 : 0;
#pragma unroll
        for (int e = 0; e < NEXP; e++)
            if (e != i0 && l[e] > l[i1]) i1 = e;
        float e1  = expf(l[i1] - l[i0]);
        float inv = 1.f / (1.f + e1);
        g_wt[2*t]   = inv;
        g_wt[2*t+1] = e1 * inv;
        int p0 = atomicAdd(&g_count[i0], 1);
        g_top_e[2*t] = i0; g_pos[2*t] = p0;
        int p1 = atomicAdd(&g_count[i1], 1);
        g_top_e[2*t+1] = i1; g_pos[2*t+1] = p1;
    }
}

// ---------------- prep: x fp16 (token order) + maps + weight conversions ---
__global__ void prep_kernel(const float* __restrict__ x,
                            const float* __restrict__ gup,
                            const float* __restrict__ dwn) {
    int b = blockIdx.x;
    if (b < TMAX) {
        int t = b;
        if (threadIdx.x == 0) {
            int s0 = expert_base(g_top_e[2*t])   + g_pos[2*t];
            int s1 = expert_base(g_top_e[2*t+1]) + g_pos[2*t+1];
            g_p2s[2*t]   = s0;
            g_p2s[2*t+1] = s1;
            g_s2t[s0] = t;
            g_s2t[s1] = t;
        }
        const float4* src = (const float4*)(x + (size_t)t * D_HID);
        __half2* dh = (__half2*)(g_x16 + (size_t)t * D_HID);
        for (int i = threadIdx.x; i < D_HID/4; i += blockDim.x) {
            float4 v = src[i];
            dh[2*i]   = __halves2half2(__float2half(v.x), __float2half(v.y));
            dh[2*i+1] = __halves2half2(__float2half(v.z), __float2half(v.w));
        }
    } else if (b < TMAX + NEXP * NGU) {
        int row = b - TMAX;
        int e = row / NGU;
        int n = row % NGU;
        int blk = n >> 6, r = n & 63;
        int src_n = (r < 32) ? (blk*32 + r) : (INTER + blk*32 + (r - 32));
        const float4* src = (const float4*)(gup + ((size_t)e * NGU + src_n) * D_HID);
        __half2* dh = (__half2*)(g_gup + (size_t)row * D_HID);
        for (int i = threadIdx.x; i < D_HID/4; i += blockDim.x) {
            float4 v = src[i];
            dh[2*i]   = __halves2half2(__float2half(v.x), __float2half(v.y));
            dh[2*i+1] = __halves2half2(__float2half(v.z), __float2half(v.w));
        }
    } else {
        int row = b - TMAX - NEXP * NGU;
        const float4* src = (const float4*)(dwn + (size_t)row * INTER);
        __half2* dh = (__half2*)(g_dwn + (size_t)row * INTER);
        for (int i = threadIdx.x; i < INTER/4; i += blockDim.x) {
            float4 v = src[i];
            dh[2*i]   = __halves2half2(__float2half(v.x), __float2half(v.y));
            dh[2*i+1] = __halves2half2(__float2half(v.z), __float2half(v.w));
        }
    }
}

// ---------------- HMMA grouped GEMM (pure fp16, SW128, hoisted indexing) ---
// CTA tile 128x128, 256 threads (8 warps: 4 in M x 2 in N), 2 CTAs/SM
// K-chunk 64 as 128 rows x 128B SW128; 3-stage pipeline.
// PHASE 0: A = g_x16 gathered via g_s2t, fused SwiGLU -> g_h (fp16)
// PHASE 1: A = g_h (slot order), fp16 epilogue -> g_ct
#define TILEB  16384
#define STAGE  (2*TILEB)
#define NSTG   3
#define GEMM_SMEM (NSTG*STAGE)       // 98304

template <int PHASE>
__global__ void __launch_bounds__(256, 2)
moe_gemm_kernel() {
    constexpr int Kd  = (PHASE == 0) ? D_HID : INTER;   // 2048 / 1408
    constexpr int NCH = Kd / 64;                        // 32 / 22
    constexpr int NROW = (PHASE == 0) ? NGU : D_HID;

    int e   = blockIdx.z;
    int cnt = g_count[e];
    int m0  = blockIdx.x * 128;
    if (m0 >= cnt) return;
    int n0  = blockIdx.y * 128;
    int off_e = expert_base(e);

    const __half* B = ((PHASE == 0) ? g_gup : g_dwn) + ((size_t)e * NROW + n0) * Kd;

    extern __shared__ __align__(128) char smem[];
    uint32_t sb = smem_u32(smem);

    int tid = threadIdx.x;
    int wid = tid >> 5;
    int lid = tid & 31;
    int warp_m = (wid >> 1) * 32;
    int warp_n = (wid & 1) * 64;

    // ---- hoisted cp.async indexing: q and (r&7) are k-invariant ----
    int rb = tid >> 3;                 // base row 0..31
    int q  = tid & 7;
    uint32_t dstbase = (uint32_t)(rb * 128 + (((q ^ (rb & 7)) << 4)));
    // per-k row = rb + 32k; dst offset = dstbase + k*4096
    const char* pa[4]; const char* pb[4]; uint32_t sza[4];
#pragma unroll
    for (int k = 0; k < 4; k++) {
        int r = rb + k * 32;
        bool v = (m0 + r) < cnt;
        sza[k] = v ? 16u : 0u;
        if (PHASE == 0) {
            int tok = v ? g_s2t[off_e + m0 + r] : 0;
            pa[k] = (const char*)(g_x16 + (size_t)tok * D_HID + q * 8);
        } else {
            pa[k] = (const char*)(g_h + (size_t)(off_e + m0 + r) * Kd + q * 8);
        }
        pb[k] = (const char*)(B + (size_t)r * Kd + q * 8);
    }

    // ---- hoisted ldsm bases: XOR folded per slice (carry-free vs offsets) --
    uint32_t m7 = (uint32_t)(lid & 7) << 4;
    uint32_t a_base = (uint32_t)(warp_m + (lid & 15)) * 128 + m7;
    uint32_t a_dq   = (uint32_t)(lid >> 4);
    uint32_t b_base = (uint32_t)(warp_n + (lid & 7) + ((lid & 16) >> 1)) * 128 + m7;
    uint32_t b_dq   = (uint32_t)((lid >> 3) & 1);
    uint32_t a_s[4], b_s[4];
#pragma unroll
    for (int sl = 0; sl < 4; sl++) {
        a_s[sl] = a_base ^ ((uint32_t)(2*sl + a_dq) << 4);
        b_s[sl] = (b_base ^ ((uint32_t)(2*sl + b_dq) << 4)) + TILEB;
    }

    float d[2][8][4];
#pragma unroll
    for (int mi = 0; mi < 2; mi++)
#pragma unroll
        for (int ni = 0; ni < 8; ni++)
#pragma unroll
            for (int k = 0; k < 4; k++) d[mi][ni][k] = 0.f;

    auto load_chunk = [&](int ci, int s) {
        uint32_t st = sb + s * STAGE;
        size_t go = (size_t)ci * 128;   // 64 halves = 128 bytes along K
#pragma unroll
        for (int k = 0; k < 4; k++) {
            uint32_t dst = st + dstbase + (uint32_t)k * 4096;
            cp16z(dst,         pa[k] + go, sza[k]);
            cp16z(dst + TILEB, pb[k] + go, 16u);
        }
    };

    load_chunk(0, 0);
    asm volatile("cp.async.commit_group;" ::: "memory");
    if (NCH > 1) load_chunk(1, 1);
    asm volatile("cp.async.commit_group;" ::: "memory");

    int sidx = 0, lidx = 2;
#pragma unroll 1
    for (int i = 0; i < NCH; i++) {
        if (i == NCH - 1) {
            asm volatile("cp.async.wait_group 0;" ::: "memory");
        } else {
            asm volatile("cp.async.wait_group 1;" ::: "memory");
        }
        __syncthreads();
        if (i + 2 < NCH) {
            load_chunk(i + 2, lidx);
            asm volatile("cp.async.commit_group;" ::: "memory");
        }
        uint32_t st = sb + sidx * STAGE;
#pragma unroll
        for (int sl = 0; sl < 4; sl++) {
            uint32_t af[2][4];
            ldsm4(af[0], st + a_s[sl]);
            ldsm4(af[1], st + a_s[sl] + 2048);
#pragma unroll
            for (int pp = 0; pp < 2; pp++) {
                uint32_t bf[2][4];
                ldsm4(bf[0], st + b_s[sl] + (uint32_t)(pp*2 + 0) * 2048);
                ldsm4(bf[1], st + b_s[sl] + (uint32_t)(pp*2 + 1) * 2048);
#pragma unroll
                for (int mi = 0; mi < 2; mi++)
#pragma unroll
                    for (int qq = 0; qq < 4; qq++)
                        mma_f16(d[mi][pp*4 + qq], af[mi], &bf[qq >> 1][(qq & 1) * 2]);
            }
        }
        sidx = (sidx == NSTG-1) ? 0 : sidx + 1;
        lidx = (lidx == NSTG-1) ? 0 : lidx + 1;
    }

    // ---------------- epilogue ----------------
    if (PHASE == 0) {
        int icb = blockIdx.y * 64 + (warp_n >> 1);
#pragma unroll
        for (int mi = 0; mi < 2; mi++) {
            int rA = warp_m + mi * 16 + (lid >> 2);
            int rB = rA + 8;
            bool vA = (m0 + rA) < cnt;
            bool vB = (m0 + rB) < cnt;
            size_t rowA = (size_t)(off_e + m0 + rA);
            size_t rowB = (size_t)(off_e + m0 + rB);
#pragma unroll
            for (int ni = 0; ni < 4; ni++) {
                int col = icb + ni * 8 + (lid & 3) * 2;
                const float* g = d[mi][ni];
                const float* u = d[mi][ni + 4];
                if (vA) {
                    float h0 = g[0] / (1.f + expf(-g[0])) * u[0];
                    float h1 = g[1] / (1.f + expf(-g[1])) * u[1];
                    *(__half2*)(g_h + rowA * INTER + col) =
                        __halves2half2(__float2half(h0), __float2half(h1));
                }
                if (vB) {
                    float h0 = g[2] / (1.f + expf(-g[2])) * u[2];
                    float h1 = g[3] / (1.f + expf(-g[3])) * u[3];
                    *(__half2*)(g_h + rowB * INTER + col) =
                        __halves2half2(__float2half(h0), __float2half(h1));
                }
            }
        }
    } else {
#pragma unroll
        for (int mi = 0; mi < 2; mi++) {
            int rA = warp_m + mi * 16 + (lid >> 2);
            int rB = rA + 8;
            bool vA = (m0 + rA) < cnt;
            bool vB = (m0 + rB) < cnt;
            __half* cA = g_ct + (size_t)(off_e + m0 + rA) * D_HID + n0 + warp_n + (lid & 3) * 2;
            __half* cB = g_ct + (size_t)(off_e + m0 + rB) * D_HID + n0 + warp_n + (lid & 3) * 2;
#pragma unroll
            for (int ni = 0; ni < 8; ni++) {
                if (vA) *(__half2*)(cA + ni * 8) =
                    __halves2half2(__float2half(d[mi][ni][0]), __float2half(d[mi][ni][1]));
                if (vB) *(__half2*)(cB + ni * 8) =
                    __halves2half2(__float2half(d[mi][ni][2]), __float2half(d[mi][ni][3]));
            }
        }
    }
}

// ---------------- combine (fp16 ct) ----------------
__global__ void combine_kernel(float* __restrict__ out, int total4) {
    int i = blockIdx.x * blockDim.x + threadIdx.x;
    if (i >= total4) return;
    int c = i % (D_HID/4);
    int t = i / (D_HID/4);
    float w0 = g_wt[2*t], w1 = g_wt[2*t+1];
    int s0 = g_p2s[2*t], s1 = g_p2s[2*t+1];
    const __half2* p0 = (const __half2*)(g_ct + (size_t)s0 * D_HID) + 2*c;
    const __half2* p1 = (const __half2*)(g_ct + (size_t)s1 * D_HID) + 2*c;
    float2 a0 = __half22float2(p0[0]);
    float2 a1 = __half22float2(p0[1]);
    float2 b0 = __half22float2(p1[0]);
    float2 b1 = __half22float2(p1[1]);
    float4 o;
    o.x = fmaf(w0, a0.x, w1 * b0.x);
    o.y = fmaf(w0, a0.y, w1 * b0.y);
    o.z = fmaf(w0, a1.x, w1 * b1.x);
    o.w = fmaf(w0, a1.y, w1 * b1.y);
    ((float4*)out)[i] = o;
}

// ---------------- launch ----------------
extern "C" void kernel_launch(void* const* d_in, const int* in_sizes, int n_in,
                              void* d_out, int out_size) {
    const float* x   = (const float*)d_in[0];
    const float* rw  = (const float*)d_in[1];
    const float* gup = (const float*)d_in[2];
    const float* dwn = (const float*)d_in[3];
    float* out = (float*)d_out;
    int T = in_sizes[0] / D_HID;

    cudaFuncSetAttribute(moe_gemm_kernel<0>, cudaFuncAttributeMaxDynamicSharedMemorySize, GEMM_SMEM);
    cudaFuncSetAttribute(moe_gemm_kernel<1>, cudaFuncAttributeMaxDynamicSharedMemorySize, GEMM_SMEM);

    zero_counts_kernel<<<1, 32>>>();                       // 0
    router_kernel<<<T, 256>>>(x, rw);                      // 1
    int prep_blocks = TMAX + NEXP * NGU + NEXP * D_HID;
    prep_kernel<<<prep_blocks, 128>>>(x, gup, dwn);        // 2

    dim3 g0(32, NGU / 128, NEXP);                          // 3 (GEMM1 @ index 3)
    moe_gemm_kernel<0><<<g0, 256, GEMM_SMEM>>>();

    dim3 g1(32, D_HID / 128, NEXP);                        // 4
    moe_gemm_kernel<1><<<g1, 256, GEMM_SMEM>>>();

    combine_kernel<<<(T * (D_HID/4) + 255) / 256, 256>>>(out, T * (D_HID/4)); // 5
}

// round 14
// speedup vs baseline: 1.4002x; 1.0378x over previous
#include <cuda_runtime.h>
#include <cuda_fp16.h>
#include <cstdint>
#include <math.h>

#define D_HID 2048
#define INTER 1408
#define NGU   2816
#define NEXP  8
#define TMAX  4096
#define TPAIR 8192
#define RMAX  9216

// ---------------- device scratch ----------------
__device__ int   g_count[NEXP];
__device__ int   g_top_e[TPAIR];
__device__ int   g_pos[TPAIR];
__device__ int   g_p2s[TPAIR];
__device__ int   g_s2t[RMAX];
__device__ float g_wt[TPAIR];
__device__ __align__(256) __half g_x16 [(size_t)TMAX * D_HID];
__device__ __align__(256) __half g_gup [(size_t)NEXP * NGU * D_HID];
__device__ __align__(256) __half g_dwn [(size_t)NEXP * D_HID * INTER];
__device__ __align__(256) __half g_h   [(size_t)RMAX * INTER];
__device__ __align__(256) __half g_ct  [(size_t)RMAX * D_HID];

// ---------------- helpers ----------------
__device__ __forceinline__ uint32_t smem_u32(const void* p) {
    uint32_t a;
    asm("{ .reg .u64 t; cvta.to.shared.u64 t, %1; cvt.u32.u64 %0, t; }" : "=r"(a) : "l"(p));
    return a;
}
__device__ __forceinline__ void cp16z(uint32_t dst, const void* src, uint32_t sz) {
    asm volatile("cp.async.cg.shared.global [%0], [%1], 16, %2;"
                 :: "r"(dst), "l"(src), "r"(sz));
}
__device__ __forceinline__ void ldsm4(uint32_t* r, uint32_t addr) {
    asm volatile("ldmatrix.sync.aligned.m8n8.x4.shared.b16 {%0,%1,%2,%3}, [%4];"
                 : "=r"(r[0]), "=r"(r[1]), "=r"(r[2]), "=r"(r[3]) : "r"(addr));
}
__device__ __forceinline__ void mma_f16(float* d, const uint32_t* a, const uint32_t* b) {
    asm volatile("mma.sync.aligned.m16n8k16.row.col.f32.f16.f16.f32 "
                 "{%0,%1,%2,%3}, {%4,%5,%6,%7}, {%8,%9}, {%0,%1,%2,%3};"
                 : "+f"(d[0]), "+f"(d[1]), "+f"(d[2]), "+f"(d[3])
                 : "r"(a[0]), "r"(a[1]), "r"(a[2]), "r"(a[3]), "r"(b[0]), "r"(b[1]));
}
__device__ __forceinline__ int expert_base(int e) {
    int o = 0;
#pragma unroll
    for (int k = 0; k < NEXP; k++)
        if (k < e) o += (g_count[k] + 127) & ~127;
    return o;
}
__device__ __forceinline__ uint4 pack8(float4 a, float4 b) {
    uint4 o;
    __half2 h0 = __floats2half2_rn(a.x, a.y);
    __half2 h1 = __floats2half2_rn(a.z, a.w);
    __half2 h2 = __floats2half2_rn(b.x, b.y);
    __half2 h3 = __floats2half2_rn(b.z, b.w);
    o.x = *reinterpret_cast<uint32_t*>(&h0);
    o.y = *reinterpret_cast<uint32_t*>(&h1);
    o.z = *reinterpret_cast<uint32_t*>(&h2);
    o.w = *reinterpret_cast<uint32_t*>(&h3);
    return o;
}

// ---------------- init ----------------
__global__ void zero_counts_kernel() {
    if (threadIdx.x < NEXP) g_count[threadIdx.x] = 0;
}

// ---------------- router (vectorized, fused x->fp16) ----------------
__global__ void router_kernel(const float* __restrict__ x,
                              const float* __restrict__ rw) {
    int t = blockIdx.x;
    int tid = threadIdx.x;               // 256; each thread owns 8 elems
    const float4* x4 = (const float4*)(x + (size_t)t * D_HID);
    float4 v0 = x4[2*tid];
    float4 v1 = x4[2*tid + 1];
    ((uint4*)(g_x16 + (size_t)t * D_HID))[tid] = pack8(v0, v1);

    float p[NEXP];
#pragma unroll
    for (int e = 0; e < NEXP; e++) {
        const float4* r4 = (const float4*)(rw + (size_t)e * D_HID);
        float4 w0 = r4[2*tid];
        float4 w1 = r4[2*tid + 1];
        float s = v0.x * w0.x;
        s = fmaf(v0.y, w0.y, s);
        s = fmaf(v0.z, w0.z, s);
        s = fmaf(v0.w, w0.w, s);
        s = fmaf(v1.x, w1.x, s);
        s = fmaf(v1.y, w1.y, s);
        s = fmaf(v1.z, w1.z, s);
        s = fmaf(v1.w, w1.w, s);
        p[e] = s;
    }
#pragma unroll
    for (int off = 16; off > 0; off >>= 1)
#pragma unroll
        for (int e = 0; e < NEXP; e++)
            p[e] += __shfl_down_sync(0xffffffffu, p[e], off);
    __shared__ float s[8][NEXP];
    int warp = tid >> 5;
    if ((tid & 31) == 0)
#pragma unroll
        for (int e = 0; e < NEXP; e++) s[warp][e] = p[e];
    __syncthreads();
    if (tid == 0) {
        float l[NEXP];
#pragma unroll
        for (int e = 0; e < NEXP; e++) {
            float a = 0.f;
#pragma unroll
            for (int w = 0; w < 8; w++) a += s[w][e];
            l[e] = a;
        }
        int i0 = 0;
#pragma unroll
        for (int e = 1; e < NEXP; e++) if (l[e] > l[i0]) i0 = e;
        int i1 = (i0 == 0) ? 1 : 0;
#pragma unroll
        for (int e = 0; e < NEXP; e++)
            if (e != i0 && l[e] > l[i1]) i1 = e;
        float e1  = expf(l[i1] - l[i0]);
        float inv = 1.f / (1.f + e1);
        g_wt[2*t]   = inv;
        g_wt[2*t+1] = e1 * inv;
        int p0 = atomicAdd(&g_count[i0], 1);
        g_top_e[2*t] = i0; g_pos[2*t] = p0;
        int p1 = atomicAdd(&g_count[i1], 1);
        g_top_e[2*t+1] = i1; g_pos[2*t+1] = p1;
    }
}

// ---------------- prep: weight conversions (16B stores) + maps -------------
#define GUP_ROWS (NEXP*NGU)    // 22528
#define DWN_ROWS (NEXP*D_HID)  // 16384
#define MAP_BLKS (TPAIR/256)   // 32
__global__ void prep_kernel(const float* __restrict__ gup,
                            const float* __restrict__ dwn) {
    int b = blockIdx.x;
    int i = threadIdx.x;       // 256
    if (b < GUP_ROWS) {
        int e = b / NGU;
        int n = b % NGU;
        int blk = n >> 6, r = n & 63;
        int src_n = (r < 32) ? (blk*32 + r) : (INTER + blk*32 + (r - 32));
        const float4* src = (const float4*)(gup + ((size_t)e * NGU + src_n) * D_HID);
        float4 a = src[2*i], c = src[2*i + 1];
        ((uint4*)(g_gup + (size_t)b * D_HID))[i] = pack8(a, c);
    } else if (b < GUP_ROWS + DWN_ROWS) {
        int row = b - GUP_ROWS;
        if (i < INTER/8) {
            const float4* src = (const float4*)(dwn + (size_t)row * INTER);
            float4 a = src[2*i], c = src[2*i + 1];
            ((uint4*)(g_dwn + (size_t)row * INTER))[i] = pack8(a, c);
        }
    } else {
        int p = (b - GUP_ROWS - DWN_ROWS) * 256 + i;
        if (p < TPAIR) {
            int sidx = expert_base(g_top_e[p]) + g_pos[p];
            g_p2s[p] = sidx;
            g_s2t[sidx] = p >> 1;
        }
    }
}

// ---------------- HMMA grouped GEMM (pure fp16, SW128, hoisted indexing) ---
// CTA tile 128x128, 256 threads (8 warps: 4 in M x 2 in N), 2 CTAs/SM
// K-chunk 64 as 128 rows x 128B SW128; 3-stage pipeline.
// PHASE 0: A = g_x16 gathered via g_s2t, fused SwiGLU -> g_h (fp16)
// PHASE 1: A = g_h (slot order), fp16 epilogue -> g_ct
#define TILEB  16384
#define STAGE  (2*TILEB)
#define NSTG   3
#define GEMM_SMEM (NSTG*STAGE)       // 98304

template <int PHASE>
__global__ void __launch_bounds__(256, 2)
moe_gemm_kernel() {
    constexpr int Kd  = (PHASE == 0) ? D_HID : INTER;   // 2048 / 1408
    constexpr int NCH = Kd / 64;                        // 32 / 22
    constexpr int NROW = (PHASE == 0) ? NGU : D_HID;

    int e   = blockIdx.z;
    int cnt = g_count[e];
    int m0  = blockIdx.x * 128;
    if (m0 >= cnt) return;
    int n0  = blockIdx.y * 128;
    int off_e = expert_base(e);

    const __half* B = ((PHASE == 0) ? g_gup : g_dwn) + ((size_t)e * NROW + n0) * Kd;

    extern __shared__ __align__(128) char smem[];
    uint32_t sb = smem_u32(smem);

    int tid = threadIdx.x;
    int wid = tid >> 5;
    int lid = tid & 31;
    int warp_m = (wid >> 1) * 32;
    int warp_n = (wid & 1) * 64;

    // ---- hoisted cp.async indexing ----
    int rb = tid >> 3;
    int q  = tid & 7;
    uint32_t dstbase = (uint32_t)(rb * 128 + (((q ^ (rb & 7)) << 4)));
    const char* pa[4]; const char* pb[4]; uint32_t sza[4];
#pragma unroll
    for (int k = 0; k < 4; k++) {
        int r = rb + k * 32;
        bool v = (m0 + r) < cnt;
        sza[k] = v ? 16u : 0u;
        if (PHASE == 0) {
            int tok = v ? g_s2t[off_e + m0 + r] : 0;
            pa[k] = (const char*)(g_x16 + (size_t)tok * D_HID + q * 8);
        } else {
            pa[k] = (const char*)(g_h + (size_t)(off_e + m0 + r) * Kd + q * 8);
        }
        pb[k] = (const char*)(B + (size_t)r * Kd + q * 8);
    }

    // ---- hoisted ldsm bases ----
    uint32_t m7 = (uint32_t)(lid & 7) << 4;
    uint32_t a_base = (uint32_t)(warp_m + (lid & 15)) * 128 + m7;
    uint32_t a_dq   = (uint32_t)(lid >> 4);
    uint32_t b_base = (uint32_t)(warp_n + (lid & 7) + ((lid & 16) >> 1)) * 128 + m7;
    uint32_t b_dq   = (uint32_t)((lid >> 3) & 1);
    uint32_t a_s[4], b_s[4];
#pragma unroll
    for (int sl = 0; sl < 4; sl++) {
        a_s[sl] = a_base ^ ((uint32_t)(2*sl + a_dq) << 4);
        b_s[sl] = (b_base ^ ((uint32_t)(2*sl + b_dq) << 4)) + TILEB;
    }

    float d[2][8][4];
#pragma unroll
    for (int mi = 0; mi < 2; mi++)
#pragma unroll
        for (int ni = 0; ni < 8; ni++)
#pragma unroll
            for (int k = 0; k < 4; k++) d[mi][ni][k] = 0.f;

    auto load_chunk = [&](int ci, int s) {
        uint32_t st = sb + s * STAGE;
        size_t go = (size_t)ci * 128;
#pragma unroll
        for (int k = 0; k < 4; k++) {
            uint32_t dst = st + dstbase + (uint32_t)k * 4096;
            cp16z(dst,         pa[k] + go, sza[k]);
            cp16z(dst + TILEB, pb[k] + go, 16u);
        }
    };

    load_chunk(0, 0);
    asm volatile("cp.async.commit_group;" ::: "memory");
    if (NCH > 1) load_chunk(1, 1);
    asm volatile("cp.async.commit_group;" ::: "memory");

    int sidx = 0, lidx = 2;
#pragma unroll 1
    for (int i = 0; i < NCH; i++) {
        if (i == NCH - 1) {
            asm volatile("cp.async.wait_group 0;" ::: "memory");
        } else {
            asm volatile("cp.async.wait_group 1;" ::: "memory");
        }
        __syncthreads();
        if (i + 2 < NCH) {
            load_chunk(i + 2, lidx);
            asm volatile("cp.async.commit_group;" ::: "memory");
        }
        uint32_t st = sb + sidx * STAGE;
#pragma unroll
        for (int sl = 0; sl < 4; sl++) {
            uint32_t af[2][4];
            ldsm4(af[0], st + a_s[sl]);
            ldsm4(af[1], st + a_s[sl] + 2048);
#pragma unroll
            for (int pp = 0; pp < 2; pp++) {
                uint32_t bf[2][4];
                ldsm4(bf[0], st + b_s[sl] + (uint32_t)(pp*2 + 0) * 2048);
                ldsm4(bf[1], st + b_s[sl] + (uint32_t)(pp*2 + 1) * 2048);
#pragma unroll
                for (int mi = 0; mi < 2; mi++)
#pragma unroll
                    for (int qq = 0; qq < 4; qq++)
                        mma_f16(d[mi][pp*4 + qq], af[mi], &bf[qq >> 1][(qq & 1) * 2]);
            }
        }
        sidx = (sidx == NSTG-1) ? 0 : sidx + 1;
        lidx = (lidx == NSTG-1) ? 0 : lidx + 1;
    }

    // ---------------- epilogue ----------------
    if (PHASE == 0) {
        int icb = blockIdx.y * 64 + (warp_n >> 1);
#pragma unroll
        for (int mi = 0; mi < 2; mi++) {
            int rA = warp_m + mi * 16 + (lid >> 2);
            int rB = rA + 8;
            bool vA = (m0 + rA) < cnt;
            bool vB = (m0 + rB) < cnt;
            size_t rowA = (size_t)(off_e + m0 + rA);
            size_t rowB = (size_t)(off_e + m0 + rB);
#pragma unroll
            for (int ni = 0; ni < 4; ni++) {
                int col = icb + ni * 8 + (lid & 3) * 2;
                const float* g = d[mi][ni];
                const float* u = d[mi][ni + 4];
                if (vA) {
                    float h0 = g[0] / (1.f + expf(-g[0])) * u[0];
                    float h1 = g[1] / (1.f + expf(-g[1])) * u[1];
                    *(__half2*)(g_h + rowA * INTER + col) = __floats2half2_rn(h0, h1);
                }
                if (vB) {
                    float h0 = g[2] / (1.f + expf(-g[2])) * u[2];
                    float h1 = g[3] / (1.f + expf(-g[3])) * u[3];
                    *(__half2*)(g_h + rowB * INTER + col) = __floats2half2_rn(h0, h1);
                }
            }
        }
    } else {
#pragma unroll
        for (int mi = 0; mi < 2; mi++) {
            int rA = warp_m + mi * 16 + (lid >> 2);
            int rB = rA + 8;
            bool vA = (m0 + rA) < cnt;
            bool vB = (m0 + rB) < cnt;
            __half* cA = g_ct + (size_t)(off_e + m0 + rA) * D_HID + n0 + warp_n + (lid & 3) * 2;
            __half* cB = g_ct + (size_t)(off_e + m0 + rB) * D_HID + n0 + warp_n + (lid & 3) * 2;
#pragma unroll
            for (int ni = 0; ni < 8; ni++) {
                if (vA) *(__half2*)(cA + ni * 8) =
                    __floats2half2_rn(d[mi][ni][0], d[mi][ni][1]);
                if (vB) *(__half2*)(cB + ni * 8) =
                    __floats2half2_rn(d[mi][ni][2], d[mi][ni][3]);
            }
        }
    }
}

// ---------------- combine (fp16 ct) ----------------
__global__ void combine_kernel(float* __restrict__ out, int total4) {
    int i = blockIdx.x * blockDim.x + threadIdx.x;
    if (i >= total4) return;
    int c = i % (D_HID/4);
    int t = i / (D_HID/4);
    float w0 = g_wt[2*t], w1 = g_wt[2*t+1];
    int s0 = g_p2s[2*t], s1 = g_p2s[2*t+1];
    const __half2* p0 = (const __half2*)(g_ct + (size_t)s0 * D_HID) + 2*c;
    const __half2* p1 = (const __half2*)(g_ct + (size_t)s1 * D_HID) + 2*c;
    float2 a0 = __half22float2(p0[0]);
    float2 a1 = __half22float2(p0[1]);
    float2 b0 = __half22float2(p1[0]);
    float2 b1 = __half22float2(p1[1]);
    float4 o;
    o.x = fmaf(w0, a0.x, w1 * b0.x);
    o.y = fmaf(w0, a0.y, w1 * b0.y);
    o.z = fmaf(w0, a1.x, w1 * b1.x);
    o.w = fmaf(w0, a1.y, w1 * b1.y);
    ((float4*)out)[i] = o;
}

// ---------------- launch ----------------
extern "C" void kernel_launch(void* const* d_in, const int* in_sizes, int n_in,
                              void* d_out, int out_size) {
    const float* x   = (const float*)d_in[0];
    const float* rw  = (const float*)d_in[1];
    const float* gup = (const float*)d_in[2];
    const float* dwn = (const float*)d_in[3];
    float* out = (float*)d_out;
    int T = in_sizes[0] / D_HID;

    cudaFuncSetAttribute(moe_gemm_kernel<0>, cudaFuncAttributeMaxDynamicSharedMemorySize, GEMM_SMEM);
    cudaFuncSetAttribute(moe_gemm_kernel<1>, cudaFuncAttributeMaxDynamicSharedMemorySize, GEMM_SMEM);

    zero_counts_kernel<<<1, 32>>>();                       // 0
    router_kernel<<<T, 256>>>(x, rw);                      // 1
    int prep_blocks = GUP_ROWS + DWN_ROWS + MAP_BLKS;      // 38944
    prep_kernel<<<prep_blocks, 256>>>(gup, dwn);           // 2

    dim3 g0(32, NGU / 128, NEXP);                          // 3 (GEMM1 @ index 3)
    moe_gemm_kernel<0><<<g0, 256, GEMM_SMEM>>>();

    dim3 g1(32, D_HID / 128, NEXP);                        // 4
    moe_gemm_kernel<1><<<g1, 256, GEMM_SMEM>>>();

    combine_kernel<<<(T * (D_HID/4) + 255) / 256, 256>>>(out, T * (D_HID/4)); // 5
}